// round 16
// baseline (speedup 1.0000x reference)
#include <cuda_runtime.h>
#include <cuda_fp16.h>
#include <math.h>
#include <stdint.h>

#define D    256
#define R    8
#define NG   64
#define NMAX 50176          // 392*128
#define NBLK 392
#define EPS  1e-5f
#define KTOT 2304           // (R+1)*D
#define NST  72             // KTOT / 32
#define BM   128
#define EMAX 1048576

// fp16 tile geometry: rows of 32 halves padded to 40 (80B, ldmatrix conflict-free)
#define LDAH  40
#define BTILEB 20480                    // bytes per B tile (256 * 80)
#define BTILEH 10240                    // halves per B tile
#define OA    0
#define OB    10240
#define STG   30720
#define NSTAGE 5
#define SMEM_TOTAL (NSTAGE * STG + 160)

// ---------------- static device scratch ----------------
__device__ __half g_Bh[3][(size_t)NST * BTILEH];     // per-layer fp16 weights, tiled
__device__ float  g_X0[(size_t)NMAX * D];
__device__ float  g_X1[(size_t)NMAX * D];
__device__ int    g_cnt[NMAX * R];
__device__ int    g_off[NMAX * R];
__device__ int    g_pos[NMAX * R];
__device__ int    g_cursor[1];
__device__ int    g_esrc[EMAX];
__device__ double g_lnstats[3][2];
__device__ float  g_pool[NG * D];
__device__ int    g_gcnt[NG];

// ---------------- helpers ----------------
__device__ __forceinline__ uint32_t smem_u32(const void* p) {
    return (uint32_t)__cvta_generic_to_shared((void*)p);
}
__device__ __forceinline__ void red_add_v4(float* addr, float4 v) {
    asm volatile("red.global.add.v4.f32 [%0], {%1,%2,%3,%4};"
                 :: "l"(addr), "f"(v.x), "f"(v.y), "f"(v.z), "f"(v.w) : "memory");
}
__device__ __forceinline__ void ldsm4(uint32_t (&r)[4], uint32_t addr) {
    asm volatile("ldmatrix.sync.aligned.m8n8.x4.shared.b16 {%0,%1,%2,%3}, [%4];"
                 : "=r"(r[0]), "=r"(r[1]), "=r"(r[2]), "=r"(r[3]) : "r"(addr));
}
__device__ __forceinline__ void mma_f16(float (&d)[4], const uint32_t (&a)[4],
                                        uint32_t b0, uint32_t b1) {
    asm volatile(
        "mma.sync.aligned.m16n8k16.row.col.f32.f16.f16.f32 "
        "{%0,%1,%2,%3}, {%4,%5,%6,%7}, {%8,%9}, {%0,%1,%2,%3};"
        : "+f"(d[0]), "+f"(d[1]), "+f"(d[2]), "+f"(d[3])
        : "r"(a[0]), "r"(a[1]), "r"(a[2]), "r"(a[3]), "r"(b0), "r"(b1));
}
__device__ __forceinline__ void mbar_init(uint32_t mb, uint32_t cnt) {
    asm volatile("mbarrier.init.shared.b64 [%0], %1;" :: "r"(mb), "r"(cnt) : "memory");
}
__device__ __forceinline__ void mbar_arrive(uint32_t mb) {
    asm volatile("mbarrier.arrive.shared.b64 _, [%0];" :: "r"(mb) : "memory");
}
__device__ __forceinline__ void mbar_expect_tx(uint32_t mb, uint32_t bytes) {
    asm volatile("mbarrier.arrive.expect_tx.shared.b64 _, [%0], %1;"
                 :: "r"(mb), "r"(bytes) : "memory");
}
__device__ __forceinline__ void mbar_wait(uint32_t mb, uint32_t ph) {
    asm volatile(
        "{\n\t.reg .pred P;\n\t"
        "LW%=:\n\t"
        "mbarrier.try_wait.parity.acquire.cta.shared::cta.b64 P, [%0], %1, 0x989680;\n\t"
        "@P bra LD%=;\n\t"
        "bra LW%=;\n\t"
        "LD%=:\n\t}"
        :: "r"(mb), "r"(ph) : "memory");
}
__device__ __forceinline__ void bulk_g2s(uint32_t dst, const void* src,
                                         uint32_t bytes, uint32_t mb) {
    asm volatile(
        "cp.async.bulk.shared::cta.global.mbarrier::complete_tx::bytes [%0], [%1], %2, [%3];"
        :: "r"(dst), "l"(src), "r"(bytes), "r"(mb) : "memory");
}
__device__ __forceinline__ void ln_params(const double* st, int M, float& mu, float& rs) {
    double m = st[0] / (double)M;
    double var = st[1] / (double)M - m * m;
    mu = (float)m;
    rs = 1.0f / ((float)sqrt(fmax(var, 0.0)) + EPS);
}

// ---------------- CSR build ----------------
__global__ void count_kernel(const int* __restrict__ dst, const int* __restrict__ et, int E) {
    int i = blockIdx.x * blockDim.x + threadIdx.x;
    if (blockIdx.x == 0) {
        if (threadIdx.x < 6) ((double*)g_lnstats)[threadIdx.x] = 0.0;
        if (threadIdx.x == 6) g_cursor[0] = 0;
    }
    if (i < E) atomicAdd(&g_cnt[dst[i] * R + et[i]], 1);
}

__global__ void scan_atomic(int L) {
    __shared__ int sh[256];
    __shared__ int sbase;
    int tid = threadIdx.x;
    int i = blockIdx.x * 256 + tid;
    int v = (i < L) ? g_cnt[i] : 0;
    sh[tid] = v; __syncthreads();
    #pragma unroll
    for (int o = 1; o < 256; o <<= 1) {
        int t = (tid >= o) ? sh[tid - o] : 0;
        __syncthreads();
        sh[tid] += t;
        __syncthreads();
    }
    if (tid == 255) sbase = atomicAdd(&g_cursor[0], sh[255]);
    __syncthreads();
    if (i < L) {
        int o = sbase + sh[tid] - v;
        g_off[i] = o;
        g_pos[i] = o;
    }
}

__global__ void place_kernel(const int* __restrict__ src, const int* __restrict__ dst,
                             const int* __restrict__ et, int E) {
    int e = blockIdx.x * blockDim.x + threadIdx.x;
    if (e < E) {
        int seg = dst[e] * R + et[e];
        int p = atomicAdd(&g_pos[seg], 1);
        g_esrc[p] = src[e];
    }
}

// ---------------- weight prep (all 3 layers in one launch; z = layer) ----------------
__global__ void prep_B(const float* __restrict__ Wrel0, const float* __restrict__ Wroot0) {
    __shared__ float s[32][33];
    int layer = blockIdx.z;
    const float* Wrel  = Wrel0  + (size_t)layer * R * D * D;
    const float* Wroot = Wroot0 + (size_t)layer * D * D;
    int k0 = blockIdx.x * 32, j0 = blockIdx.y * 32;
    int kt = blockIdx.x;
    for (int i = threadIdx.y; i < 32; i += 8) {
        int k = k0 + i;
        const float* row = (k < R * D) ? (Wrel + (size_t)k * D)
                                       : (Wroot + (size_t)(k - R * D) * D);
        s[i][threadIdx.x] = row[j0 + threadIdx.x];
    }
    __syncthreads();
    for (int i = threadIdx.y; i < 32; i += 8) {
        int j = j0 + i;
        g_Bh[layer][(size_t)kt * BTILEH + j * LDAH + threadIdx.x] =
            __float2half_rn(s[threadIdx.x][i]);
    }
}

// ---------------- fused warp-specialized GEMM (fp16, decoupled consumers) ----------------
// 384 threads: warps 0-7 consumers (MMA), warps 8-11 producers (A gather).
__global__ __launch_bounds__(384, 1) void rgcn_fused(
    const float* __restrict__ Xcur,
    const __half* __restrict__ Bh,
    const float* __restrict__ bconv,
    float* __restrict__ Xnext, int Nn,
    const float* __restrict__ pw, const float* __restrict__ pb,
    const double* __restrict__ statsPrev,
    double* __restrict__ statsOut, int M)
{
    extern __shared__ char sm[];
    uint32_t sbase = smem_u32(sm);
    uint32_t mb_bfull  = sbase + NSTAGE * STG;        // 5 x 8B
    uint32_t mb_afull  = mb_bfull + 40;               // 5 x 8B
    uint32_t mb_aempty = mb_afull + 40;               // 5 x 8B
    int tid = threadIdx.x, lane = tid & 31, wid = tid >> 5;
    int row0 = blockIdx.x * BM;

    float mu = 0.f, rs = 0.f;
    bool ln = (statsPrev != nullptr);
    if (ln) ln_params(statsPrev, M, mu, rs);

    if (tid == 0) {
        #pragma unroll
        for (int s = 0; s < NSTAGE; s++) {
            mbar_init(mb_bfull + s * 8, 1);
            mbar_init(mb_afull + s * 8, 128);
            mbar_init(mb_aempty + s * 8, 8);          // one arrive per consumer warp
        }
    }
    __syncthreads();
    if (tid == 0) {
        #pragma unroll
        for (int s = 0; s < NSTAGE; s++) {
            mbar_expect_tx(mb_bfull + s * 8, BTILEB);
            bulk_g2s(sbase + s * STG + OB, Bh + (size_t)s * BTILEH, BTILEB, mb_bfull + s * 8);
        }
    }

    if (wid >= 8) {
        // ================= PRODUCER: 128 threads, one node each =================
        int fn = tid - 256;
        int fnode = row0 + fn;
        bool fvalid = fnode < Nn;

        int pcnt[8], poff[8];
        #pragma unroll
        for (int r = 0; r < 8; r++) {
            pcnt[r] = fvalid ? __ldg(&g_cnt[fnode * R + r]) : 0;
            poff[r] = fvalid ? __ldg(&g_off[fnode * R + r]) : 0;
        }

        int cidx[8];
        int ccnt = 0, coff = 0;

        #pragma unroll 1
        for (int kt = 0; kt < NST; kt++) {
            int s = kt % NSTAGE;
            if (kt >= NSTAGE)
                mbar_wait(mb_aempty + s * 8, ((kt / NSTAGE) + 1) & 1);
            float v[32];
            #pragma unroll
            for (int q = 0; q < 32; q++) v[q] = 0.f;

            if (kt < 64) {
                int r = kt >> 3, ch = kt & 7;
                if (ch == 0) {
                    ccnt = pcnt[r];
                    coff = poff[r];
                    #pragma unroll
                    for (int i = 0; i < 8; i++)
                        cidx[i] = (i < ccnt) ? __ldg(&g_esrc[coff + i]) : 0;
                }
                int cbase = ch * 32;
                if (ccnt > 0) {
                    int i = 0;
                    int lim = (ccnt < 8) ? ccnt : 8;
                    for (; i + 2 <= lim; i += 2) {
                        const float4* xa = (const float4*)(Xcur + (size_t)cidx[i] * D + cbase);
                        const float4* xb = (const float4*)(Xcur + (size_t)cidx[i + 1] * D + cbase);
                        #pragma unroll
                        for (int g = 0; g < 8; g++) {
                            float4 p = __ldg(xa + g);
                            float4 q = __ldg(xb + g);
                            v[g * 4 + 0] += p.x + q.x; v[g * 4 + 1] += p.y + q.y;
                            v[g * 4 + 2] += p.z + q.z; v[g * 4 + 3] += p.w + q.w;
                        }
                    }
                    if (i < lim) {
                        const float4* xa = (const float4*)(Xcur + (size_t)cidx[i] * D + cbase);
                        #pragma unroll
                        for (int g = 0; g < 8; g++) {
                            float4 p = __ldg(xa + g);
                            v[g * 4 + 0] += p.x; v[g * 4 + 1] += p.y;
                            v[g * 4 + 2] += p.z; v[g * 4 + 3] += p.w;
                        }
                    }
                    for (int j = 8; j < ccnt; j++) {
                        int sidx = __ldg(&g_esrc[coff + j]);
                        const float4* xa = (const float4*)(Xcur + (size_t)sidx * D + cbase);
                        #pragma unroll
                        for (int g = 0; g < 8; g++) {
                            float4 p = __ldg(xa + g);
                            v[g * 4 + 0] += p.x; v[g * 4 + 1] += p.y;
                            v[g * 4 + 2] += p.z; v[g * 4 + 3] += p.w;
                        }
                    }
                    float sc = 1.0f / (float)ccnt;
                    #pragma unroll
                    for (int q = 0; q < 32; q++) v[q] *= sc;
                    if (ln) {
                        #pragma unroll
                        for (int q = 0; q < 32; q++)
                            v[q] = pw[cbase + q] * ((v[q] - mu) * rs) + pb[cbase + q];
                    }
                }
            } else {
                int cbase = (kt - 64) * 32;
                if (fvalid) {
                    const float4* xp = (const float4*)(Xcur + (size_t)fnode * D + cbase);
                    #pragma unroll
                    for (int g = 0; g < 8; g++) {
                        float4 p = __ldg(xp + g);
                        v[g * 4 + 0] = p.x; v[g * 4 + 1] = p.y;
                        v[g * 4 + 2] = p.z; v[g * 4 + 3] = p.w;
                    }
                    if (ln) {
                        #pragma unroll
                        for (int q = 0; q < 32; q++)
                            v[q] = pw[cbase + q] * ((v[q] - mu) * rs) + pb[cbase + q];
                    }
                }
            }
            uint32_t w16[16];
            #pragma unroll
            for (int p2 = 0; p2 < 16; p2++) {
                __half2 h = __floats2half2_rn(v[2 * p2], v[2 * p2 + 1]);
                w16[p2] = *reinterpret_cast<uint32_t*>(&h);
            }
            uint32_t* dst = (uint32_t*)(sm + s * STG + OA + fn * (LDAH * 2));
            *(uint4*)(dst + 0)  = make_uint4(w16[0],  w16[1],  w16[2],  w16[3]);
            *(uint4*)(dst + 4)  = make_uint4(w16[4],  w16[5],  w16[6],  w16[7]);
            *(uint4*)(dst + 8)  = make_uint4(w16[8],  w16[9],  w16[10], w16[11]);
            *(uint4*)(dst + 12) = make_uint4(w16[12], w16[13], w16[14], w16[15]);
            mbar_arrive(mb_afull + s * 8);
        }
        return;
    }

    // ================= CONSUMER: 256 threads, decoupled warps =================
    int wm = wid & 1, wn = wid >> 1;
    float acc[4][8][4];
    #pragma unroll
    for (int i = 0; i < 4; i++)
        #pragma unroll
        for (int j = 0; j < 8; j++)
            #pragma unroll
            for (int q = 0; q < 4; q++) acc[i][j][q] = 0.f;

    uint32_t aoff = (uint32_t)((wm * 64 + (lane & 15)) * (LDAH * 2) + ((lane >> 4) << 4));
    uint32_t boff = (uint32_t)((wn * 64 + (lane & 15)) * (LDAH * 2) + ((lane >> 4) << 4));

    #pragma unroll 1
    for (int kt = 0; kt < NST; kt++) {
        int b = kt % NSTAGE;
        uint32_t ph = (kt / NSTAGE) & 1;
        mbar_wait(mb_bfull + b * 8, ph);
        mbar_wait(mb_afull + b * 8, ph);

        uint32_t sb = sbase + b * STG;
        #pragma unroll
        for (int ks = 0; ks < 2; ks++) {
            uint32_t koff = ks * 32;
            uint32_t ah[4][4];
            #pragma unroll
            for (int mi = 0; mi < 4; mi++)
                ldsm4(ah[mi], sb + OA + aoff + mi * 16 * (LDAH * 2) + koff);
            #pragma unroll
            for (int nj2 = 0; nj2 < 4; nj2++) {
                uint32_t bf[4];
                ldsm4(bf, sb + OB + boff + nj2 * 16 * (LDAH * 2) + koff);
                #pragma unroll
                for (int mi = 0; mi < 4; mi++) {
                    mma_f16(acc[mi][nj2 * 2],     ah[mi], bf[0], bf[2]);
                    mma_f16(acc[mi][nj2 * 2 + 1], ah[mi], bf[1], bf[3]);
                }
            }
        }
        // each consumer warp signals done-with-stage; warp0 drains + refetches B
        if (lane == 0) mbar_arrive(mb_aempty + b * 8);
        if (wid == 0 && lane == 0 && kt + NSTAGE < NST) {
            mbar_wait(mb_aempty + b * 8, ph);   // all 8 warps done with stage b
            mbar_expect_tx(mb_bfull + b * 8, BTILEB);
            bulk_g2s(sbase + b * STG + OB, Bh + (size_t)(kt + NSTAGE) * BTILEH,
                     BTILEB, mb_bfull + b * 8);
        }
    }

    // ---- epilogue: bias + residual(affine) + relu + stats ----
    int fr = lane >> 2, fc = lane & 3;
    float ps = 0.f, pq = 0.f;
    #pragma unroll
    for (int mi = 0; mi < 4; mi++) {
        #pragma unroll
        for (int half = 0; half < 2; half++) {
            int n = row0 + wm * 64 + mi * 16 + fr + half * 8;
            if (n >= Nn) continue;
            #pragma unroll
            for (int nj = 0; nj < 8; nj++) {
                int col = wn * 64 + nj * 8 + fc * 2;
                float2 xv = *(const float2*)(Xcur + (size_t)n * D + col);
                float2 bv = *(const float2*)(bconv + col);
                if (ln) {
                    float2 wv = *(const float2*)(pw + col);
                    float2 bb = *(const float2*)(pb + col);
                    xv.x = wv.x * ((xv.x - mu) * rs) + bb.x;
                    xv.y = wv.y * ((xv.y - mu) * rs) + bb.y;
                }
                float2 o;
                o.x = fmaxf(acc[mi][nj][half * 2 + 0] + bv.x + xv.x, 0.f);
                o.y = fmaxf(acc[mi][nj][half * 2 + 1] + bv.y + xv.y, 0.f);
                *(float2*)(Xnext + (size_t)n * D + col) = o;
                ps += o.x + o.y;
                pq += o.x * o.x + o.y * o.y;
            }
        }
    }
    if (statsOut != nullptr) {
        #pragma unroll
        for (int o = 16; o > 0; o >>= 1) {
            ps += __shfl_down_sync(0xffffffffu, ps, o);
            pq += __shfl_down_sync(0xffffffffu, pq, o);
        }
        if (lane == 0) {
            atomicAdd(&statsOut[0], (double)ps);
            atomicAdd(&statsOut[1], (double)pq);
        }
    }
}

// ---------------- global mean pool + head ----------------
__global__ void pool_cnt(const int* __restrict__ batch, int Nn) {
    int i = blockIdx.x * blockDim.x + threadIdx.x;
    if (i < Nn) atomicAdd(&g_gcnt[batch[i]], 1);
}
__global__ void pool_sum(const float* __restrict__ X, const int* __restrict__ batch, int Nn) {
    int idx = blockIdx.x * blockDim.x + threadIdx.x;
    if (idx >= Nn * (D / 4)) return;
    int n = idx >> 6, c = idx & 63;
    float4 v = ((const float4*)X)[(size_t)n * (D / 4) + c];
    red_add_v4(g_pool + batch[n] * D + c * 4, v);
}
__global__ void head_kernel(const float* __restrict__ W1, const float* __restrict__ b1,
                            const float* __restrict__ W2, const float* __restrict__ b2,
                            const float* __restrict__ W3, const float* __restrict__ b3,
                            float* __restrict__ out) {
    __shared__ float g[D], h1[D], h2[D];
    int bg = blockIdx.x, j = threadIdx.x;
    float c = fmaxf((float)g_gcnt[bg], 1.f);
    g[j] = g_pool[bg * D + j] / c;
    __syncthreads();
    float acc = b1[j];
    for (int k = 0; k < D; k++) acc = fmaf(g[k], W1[k * D + j], acc);
    h1[j] = fmaxf(acc, 0.f);
    __syncthreads();
    acc = b2[j];
    for (int k = 0; k < D; k++) acc = fmaf(h1[k], W2[k * D + j], acc);
    h2[j] = fmaxf(acc, 0.f);
    __syncthreads();
    if (j < 4) {
        acc = b3[j];
        for (int k = 0; k < D; k++) acc = fmaf(h2[k], W3[k * 4 + j], acc);
        out[bg * 4 + j] = acc;
    }
}

// ---------------- launch ----------------
extern "C" void kernel_launch(void* const* d_in, const int* in_sizes, int n_in,
                              void* d_out, int out_size) {
    const float* x      = (const float*)d_in[0];
    const int*   ei     = (const int*)d_in[1];
    const int*   et     = (const int*)d_in[2];
    const int*   batch  = (const int*)d_in[3];
    const float* W_rel  = (const float*)d_in[4];
    const float* W_root = (const float*)d_in[5];
    const float* b_conv = (const float*)d_in[6];
    const float* ln_w   = (const float*)d_in[7];
    const float* ln_b   = (const float*)d_in[8];
    const float* W1 = (const float*)d_in[9];
    const float* b1 = (const float*)d_in[10];
    const float* W2 = (const float*)d_in[11];
    const float* b2 = (const float*)d_in[12];
    const float* W3 = (const float*)d_in[13];
    const float* b3 = (const float*)d_in[14];

    int E  = in_sizes[1] / 2;
    int Nn = in_sizes[0] / D;
    int M  = Nn * D;
    const int* src = ei;
    const int* dst = ei + E;
    int L = Nn * R;
    int nb = (L + 255) / 256;

    cudaFuncSetAttribute(rgcn_fused, cudaFuncAttributeMaxDynamicSharedMemorySize, SMEM_TOTAL);

    void *pCnt, *pStats, *pPool, *pGcnt, *pBh;
    cudaGetSymbolAddress(&pCnt, g_cnt);
    cudaGetSymbolAddress(&pStats, g_lnstats);
    cudaGetSymbolAddress(&pPool, g_pool);
    cudaGetSymbolAddress(&pGcnt, g_gcnt);
    cudaGetSymbolAddress(&pBh, g_Bh);
    double* pst = (double*)pStats;
    const __half* Bh0 = (const __half*)pBh;

    cudaMemsetAsync(pCnt, 0, (size_t)NMAX * R * sizeof(int));
    // launch order: prep(1) count(2) scan(3) place(4) rgcn0(5) rgcn1(6=ncu slot) ...
    prep_B<<<dim3(NST, D / 32, 3), dim3(32, 8)>>>(W_rel, W_root);
    count_kernel<<<(E + 255) / 256, 256>>>(dst, et, E);
    scan_atomic<<<nb, 256>>>(L);
    place_kernel<<<(E + 255) / 256, 256>>>(src, dst, et, E);

    const float* cur = x;
    float* bufs[2];
    cudaGetSymbolAddress((void**)&bufs[0], g_X0);
    cudaGetSymbolAddress((void**)&bufs[1], g_X1);

    for (int l = 0; l < 3; l++) {
        const double* sp = (l > 0) ? (pst + (l - 1) * 2) : nullptr;
        const float* pw = (l > 0) ? (ln_w + (l - 1) * D) : nullptr;
        const float* pb = (l > 0) ? (ln_b + (l - 1) * D) : nullptr;
        float* nxt = bufs[l & 1];
        double* so = (l < 2) ? (pst + l * 2) : nullptr;
        rgcn_fused<<<NBLK, 384, SMEM_TOTAL>>>(
            cur, Bh0 + (size_t)l * NST * BTILEH, b_conv + l * D, nxt, Nn,
            pw, pb, sp, so, M);
        cur = nxt;
    }

    cudaMemsetAsync(pPool, 0, NG * D * sizeof(float));
    cudaMemsetAsync(pGcnt, 0, NG * sizeof(int));
    pool_cnt<<<(Nn + 255) / 256, 256>>>(batch, Nn);
    pool_sum<<<(Nn * (D / 4) + 255) / 256, 256>>>(cur, batch, Nn);
    head_kernel<<<NG, D>>>(W1, b1, W2, b2, W3, b3, (float*)d_out);
}

// round 17
// speedup vs baseline: 1.0137x; 1.0137x over previous
#include <cuda_runtime.h>
#include <cuda_fp16.h>
#include <math.h>
#include <stdint.h>

#define D    256
#define R    8
#define NG   64
#define NMAX 50176          // 392*128
#define NBLK 392
#define EPS  1e-5f
#define KTOT 2304           // (R+1)*D
#define NST  72             // KTOT / 32
#define BM   128
#define EMAX 1048576

// fp16 tile geometry: rows of 32 halves padded to 40 (80B, ldmatrix conflict-free)
#define LDAH  40
#define BTILEB 20480                    // bytes per B tile (256 * 80)
#define BTILEH 10240                    // halves per B tile
#define OA    0
#define OB    10240
#define STG   30720
#define NSTAGE 6
#define SMEM_TOTAL (NSTAGE * STG + 192)

// ---------------- static device scratch ----------------
__device__ __half g_Bh[3][(size_t)NST * BTILEH];     // per-layer fp16 weights, tiled
__device__ float  g_X0[(size_t)NMAX * D];
__device__ float  g_X1[(size_t)NMAX * D];
__device__ int    g_cnt[NMAX * R];
__device__ int    g_off[NMAX * R];
__device__ int    g_pos[NMAX * R];
__device__ int    g_cursor[1];
__device__ int    g_esrc[EMAX];
__device__ double g_lnstats[3][2];
__device__ float  g_pool[NG * D];
__device__ int    g_gcnt[NG];

// ---------------- helpers ----------------
__device__ __forceinline__ uint32_t smem_u32(const void* p) {
    return (uint32_t)__cvta_generic_to_shared((void*)p);
}
__device__ __forceinline__ void red_add_v4(float* addr, float4 v) {
    asm volatile("red.global.add.v4.f32 [%0], {%1,%2,%3,%4};"
                 :: "l"(addr), "f"(v.x), "f"(v.y), "f"(v.z), "f"(v.w) : "memory");
}
__device__ __forceinline__ void ldsm4(uint32_t (&r)[4], uint32_t addr) {
    asm volatile("ldmatrix.sync.aligned.m8n8.x4.shared.b16 {%0,%1,%2,%3}, [%4];"
                 : "=r"(r[0]), "=r"(r[1]), "=r"(r[2]), "=r"(r[3]) : "r"(addr));
}
__device__ __forceinline__ void mma_f16(float (&d)[4], const uint32_t (&a)[4],
                                        uint32_t b0, uint32_t b1) {
    asm volatile(
        "mma.sync.aligned.m16n8k16.row.col.f32.f16.f16.f32 "
        "{%0,%1,%2,%3}, {%4,%5,%6,%7}, {%8,%9}, {%0,%1,%2,%3};"
        : "+f"(d[0]), "+f"(d[1]), "+f"(d[2]), "+f"(d[3])
        : "r"(a[0]), "r"(a[1]), "r"(a[2]), "r"(a[3]), "r"(b0), "r"(b1));
}
__device__ __forceinline__ void mbar_init(uint32_t mb, uint32_t cnt) {
    asm volatile("mbarrier.init.shared.b64 [%0], %1;" :: "r"(mb), "r"(cnt) : "memory");
}
__device__ __forceinline__ void mbar_arrive(uint32_t mb) {
    asm volatile("mbarrier.arrive.shared.b64 _, [%0];" :: "r"(mb) : "memory");
}
__device__ __forceinline__ void mbar_expect_tx(uint32_t mb, uint32_t bytes) {
    asm volatile("mbarrier.arrive.expect_tx.shared.b64 _, [%0], %1;"
                 :: "r"(mb), "r"(bytes) : "memory");
}
__device__ __forceinline__ void mbar_wait(uint32_t mb, uint32_t ph) {
    asm volatile(
        "{\n\t.reg .pred P;\n\t"
        "LW%=:\n\t"
        "mbarrier.try_wait.parity.acquire.cta.shared::cta.b64 P, [%0], %1, 0x989680;\n\t"
        "@P bra LD%=;\n\t"
        "bra LW%=;\n\t"
        "LD%=:\n\t}"
        :: "r"(mb), "r"(ph) : "memory");
}
__device__ __forceinline__ void bulk_g2s(uint32_t dst, const void* src,
                                         uint32_t bytes, uint32_t mb) {
    asm volatile(
        "cp.async.bulk.shared::cta.global.mbarrier::complete_tx::bytes [%0], [%1], %2, [%3];"
        :: "r"(dst), "l"(src), "r"(bytes), "r"(mb) : "memory");
}
__device__ __forceinline__ void ln_params(const double* st, int M, float& mu, float& rs) {
    double m = st[0] / (double)M;
    double var = st[1] / (double)M - m * m;
    mu = (float)m;
    rs = 1.0f / ((float)sqrt(fmax(var, 0.0)) + EPS);
}

// ---------------- CSR build ----------------
__global__ void count_kernel(const int* __restrict__ dst, const int* __restrict__ et, int E) {
    int i = blockIdx.x * blockDim.x + threadIdx.x;
    if (blockIdx.x == 0) {
        if (threadIdx.x < 6) ((double*)g_lnstats)[threadIdx.x] = 0.0;
        if (threadIdx.x == 6) g_cursor[0] = 0;
    }
    if (i < E) atomicAdd(&g_cnt[dst[i] * R + et[i]], 1);
}

__global__ void scan_atomic(int L) {
    __shared__ int sh[256];
    __shared__ int sbase;
    int tid = threadIdx.x;
    int i = blockIdx.x * 256 + tid;
    int v = (i < L) ? g_cnt[i] : 0;
    sh[tid] = v; __syncthreads();
    #pragma unroll
    for (int o = 1; o < 256; o <<= 1) {
        int t = (tid >= o) ? sh[tid - o] : 0;
        __syncthreads();
        sh[tid] += t;
        __syncthreads();
    }
    if (tid == 255) sbase = atomicAdd(&g_cursor[0], sh[255]);
    __syncthreads();
    if (i < L) {
        int o = sbase + sh[tid] - v;
        g_off[i] = o;
        g_pos[i] = o;
    }
}

__global__ void place_kernel(const int* __restrict__ src, const int* __restrict__ dst,
                             const int* __restrict__ et, int E) {
    int e = blockIdx.x * blockDim.x + threadIdx.x;
    if (e < E) {
        int seg = dst[e] * R + et[e];
        int p = atomicAdd(&g_pos[seg], 1);
        g_esrc[p] = src[e];
    }
}

// ---------------- weight prep (all 3 layers; z = layer) ----------------
__global__ void prep_B(const float* __restrict__ Wrel0, const float* __restrict__ Wroot0) {
    __shared__ float s[32][33];
    int layer = blockIdx.z;
    const float* Wrel  = Wrel0  + (size_t)layer * R * D * D;
    const float* Wroot = Wroot0 + (size_t)layer * D * D;
    int k0 = blockIdx.x * 32, j0 = blockIdx.y * 32;
    int kt = blockIdx.x;
    for (int i = threadIdx.y; i < 32; i += 8) {
        int k = k0 + i;
        const float* row = (k < R * D) ? (Wrel + (size_t)k * D)
                                       : (Wroot + (size_t)(k - R * D) * D);
        s[i][threadIdx.x] = row[j0 + threadIdx.x];
    }
    __syncthreads();
    for (int i = threadIdx.y; i < 32; i += 8) {
        int j = j0 + i;
        g_Bh[layer][(size_t)kt * BTILEH + j * LDAH + threadIdx.x] =
            __float2half_rn(s[threadIdx.x][i]);
    }
}

// ---------------- fused warp-specialized GEMM (fp16) ----------------
// 384 threads: warps 0-7 consumers (MMA), warps 8-11 producers (A gather).
__global__ __launch_bounds__(384, 1) void rgcn_fused(
    const float* __restrict__ Xcur,
    const __half* __restrict__ Bh,
    const float* __restrict__ bconv,
    float* __restrict__ Xnext, int Nn,
    const float* __restrict__ pw, const float* __restrict__ pb,
    const double* __restrict__ statsPrev,
    double* __restrict__ statsOut, int M)
{
    extern __shared__ char sm[];
    uint32_t sbase = smem_u32(sm);
    uint32_t mb_bfull  = sbase + NSTAGE * STG;        // 6 x 8B
    uint32_t mb_afull  = mb_bfull + 48;               // 6 x 8B
    uint32_t mb_aempty = mb_afull + 48;               // 6 x 8B
    int tid = threadIdx.x, lane = tid & 31, wid = tid >> 5;
    int row0 = blockIdx.x * BM;

    float mu = 0.f, rs = 0.f;
    bool ln = (statsPrev != nullptr);
    if (ln) ln_params(statsPrev, M, mu, rs);

    if (tid == 0) {
        #pragma unroll
        for (int s = 0; s < NSTAGE; s++) {
            mbar_init(mb_bfull + s * 8, 1);
            mbar_init(mb_afull + s * 8, 128);
            mbar_init(mb_aempty + s * 8, 1);
        }
    }
    __syncthreads();
    if (tid == 0) {
        #pragma unroll
        for (int s = 0; s < NSTAGE; s++) {
            mbar_expect_tx(mb_bfull + s * 8, BTILEB);
            bulk_g2s(sbase + s * STG + OB, Bh + (size_t)s * BTILEH, BTILEB, mb_bfull + s * 8);
        }
    }

    if (wid >= 8) {
        // ================= PRODUCER: 128 threads, one node each =================
        int fn = tid - 256;
        int fnode = row0 + fn;
        bool fvalid = fnode < Nn;

        int pcnt[8], poff[8];
        #pragma unroll
        for (int r = 0; r < 8; r++) {
            pcnt[r] = fvalid ? __ldg(&g_cnt[fnode * R + r]) : 0;
            poff[r] = fvalid ? __ldg(&g_off[fnode * R + r]) : 0;
        }

        int cidx[8], nidx[8];
        int ccnt = 0, coff = 0;
        // initial prefetch: relation 0
        {
            int c0 = pcnt[0], o0 = poff[0];
            #pragma unroll
            for (int i = 0; i < 8; i++)
                nidx[i] = (i < c0) ? __ldg(&g_esrc[o0 + i]) : 0;
        }

        #pragma unroll 1
        for (int kt = 0; kt < NST; kt++) {
            int s = kt % NSTAGE;
            if (kt >= NSTAGE)
                mbar_wait(mb_aempty + s * 8, ((kt / NSTAGE) + 1) & 1);
            float v[32];
            #pragma unroll
            for (int q = 0; q < 32; q++) v[q] = 0.f;

            if (kt < 64) {
                int r = kt >> 3, ch = kt & 7;
                if (ch == 0) {
                    // adopt prefetched indices for this relation
                    ccnt = pcnt[r];
                    coff = poff[r];
                    #pragma unroll
                    for (int i = 0; i < 8; i++) cidx[i] = nidx[i];
                }
                if (ch == 4 && r < 7) {
                    // prefetch next relation's indices (latency hidden over chunks 5-7)
                    int cn = pcnt[r + 1], on = poff[r + 1];
                    #pragma unroll
                    for (int i = 0; i < 8; i++)
                        nidx[i] = (i < cn) ? __ldg(&g_esrc[on + i]) : 0;
                }
                int cbase = ch * 32;
                if (ccnt > 0) {
                    int i = 0;
                    int lim = (ccnt < 8) ? ccnt : 8;
                    for (; i + 2 <= lim; i += 2) {
                        const float4* xa = (const float4*)(Xcur + (size_t)cidx[i] * D + cbase);
                        const float4* xb = (const float4*)(Xcur + (size_t)cidx[i + 1] * D + cbase);
                        #pragma unroll
                        for (int g = 0; g < 8; g++) {
                            float4 p = __ldg(xa + g);
                            float4 q = __ldg(xb + g);
                            v[g * 4 + 0] += p.x + q.x; v[g * 4 + 1] += p.y + q.y;
                            v[g * 4 + 2] += p.z + q.z; v[g * 4 + 3] += p.w + q.w;
                        }
                    }
                    if (i < lim) {
                        const float4* xa = (const float4*)(Xcur + (size_t)cidx[i] * D + cbase);
                        #pragma unroll
                        for (int g = 0; g < 8; g++) {
                            float4 p = __ldg(xa + g);
                            v[g * 4 + 0] += p.x; v[g * 4 + 1] += p.y;
                            v[g * 4 + 2] += p.z; v[g * 4 + 3] += p.w;
                        }
                    }
                    for (int j = 8; j < ccnt; j++) {
                        int sidx = __ldg(&g_esrc[coff + j]);
                        const float4* xa = (const float4*)(Xcur + (size_t)sidx * D + cbase);
                        #pragma unroll
                        for (int g = 0; g < 8; g++) {
                            float4 p = __ldg(xa + g);
                            v[g * 4 + 0] += p.x; v[g * 4 + 1] += p.y;
                            v[g * 4 + 2] += p.z; v[g * 4 + 3] += p.w;
                        }
                    }
                    float sc = 1.0f / (float)ccnt;
                    #pragma unroll
                    for (int q = 0; q < 32; q++) v[q] *= sc;
                    if (ln) {
                        #pragma unroll
                        for (int q = 0; q < 32; q++)
                            v[q] = pw[cbase + q] * ((v[q] - mu) * rs) + pb[cbase + q];
                    }
                }
            } else {
                int cbase = (kt - 64) * 32;
                if (fvalid) {
                    const float4* xp = (const float4*)(Xcur + (size_t)fnode * D + cbase);
                    #pragma unroll
                    for (int g = 0; g < 8; g++) {
                        float4 p = __ldg(xp + g);
                        v[g * 4 + 0] = p.x; v[g * 4 + 1] = p.y;
                        v[g * 4 + 2] = p.z; v[g * 4 + 3] = p.w;
                    }
                    if (ln) {
                        #pragma unroll
                        for (int q = 0; q < 32; q++)
                            v[q] = pw[cbase + q] * ((v[q] - mu) * rs) + pb[cbase + q];
                    }
                }
            }
            uint32_t w16[16];
            #pragma unroll
            for (int p2 = 0; p2 < 16; p2++) {
                __half2 h = __floats2half2_rn(v[2 * p2], v[2 * p2 + 1]);
                w16[p2] = *reinterpret_cast<uint32_t*>(&h);
            }
            uint32_t* dst = (uint32_t*)(sm + s * STG + OA + fn * (LDAH * 2));
            *(uint4*)(dst + 0)  = make_uint4(w16[0],  w16[1],  w16[2],  w16[3]);
            *(uint4*)(dst + 4)  = make_uint4(w16[4],  w16[5],  w16[6],  w16[7]);
            *(uint4*)(dst + 8)  = make_uint4(w16[8],  w16[9],  w16[10], w16[11]);
            *(uint4*)(dst + 12) = make_uint4(w16[12], w16[13], w16[14], w16[15]);
            mbar_arrive(mb_afull + s * 8);
        }
        return;
    }

    // ================= CONSUMER: 256 threads, pure MMA =================
    int wm = wid & 1, wn = wid >> 1;
    float acc[4][8][4];
    #pragma unroll
    for (int i = 0; i < 4; i++)
        #pragma unroll
        for (int j = 0; j < 8; j++)
            #pragma unroll
            for (int q = 0; q < 4; q++) acc[i][j][q] = 0.f;

    uint32_t aoff = (uint32_t)((wm * 64 + (lane & 15)) * (LDAH * 2) + ((lane >> 4) << 4));
    uint32_t boff = (uint32_t)((wn * 64 + (lane & 15)) * (LDAH * 2) + ((lane >> 4) << 4));

    #pragma unroll 1
    for (int kt = 0; kt < NST; kt++) {
        int b = kt % NSTAGE;
        uint32_t ph = (kt / NSTAGE) & 1;
        mbar_wait(mb_bfull + b * 8, ph);
        mbar_wait(mb_afull + b * 8, ph);

        uint32_t sb = sbase + b * STG;
        #pragma unroll
        for (int ks = 0; ks < 2; ks++) {
            uint32_t koff = ks * 32;
            uint32_t ah[4][4];
            #pragma unroll
            for (int mi = 0; mi < 4; mi++)
                ldsm4(ah[mi], sb + OA + aoff + mi * 16 * (LDAH * 2) + koff);
            #pragma unroll
            for (int nj2 = 0; nj2 < 4; nj2++) {
                uint32_t bf[4];
                ldsm4(bf, sb + OB + boff + nj2 * 16 * (LDAH * 2) + koff);
                #pragma unroll
                for (int mi = 0; mi < 4; mi++) {
                    mma_f16(acc[mi][nj2 * 2],     ah[mi], bf[0], bf[2]);
                    mma_f16(acc[mi][nj2 * 2 + 1], ah[mi], bf[1], bf[3]);
                }
            }
        }
        asm volatile("bar.sync 1, 256;" ::: "memory");
        if (tid == 0) {
            if (kt + NSTAGE < NST) {
                mbar_expect_tx(mb_bfull + b * 8, BTILEB);
                bulk_g2s(sbase + b * STG + OB, Bh + (size_t)(kt + NSTAGE) * BTILEH,
                         BTILEB, mb_bfull + b * 8);
            }
            mbar_arrive(mb_aempty + b * 8);
        }
    }

    // ---- epilogue: bias + residual(affine) + relu + stats ----
    int fr = lane >> 2, fc = lane & 3;
    float ps = 0.f, pq = 0.f;
    #pragma unroll
    for (int mi = 0; mi < 4; mi++) {
        #pragma unroll
        for (int half = 0; half < 2; half++) {
            int n = row0 + wm * 64 + mi * 16 + fr + half * 8;
            if (n >= Nn) continue;
            #pragma unroll
            for (int nj = 0; nj < 8; nj++) {
                int col = wn * 64 + nj * 8 + fc * 2;
                float2 xv = *(const float2*)(Xcur + (size_t)n * D + col);
                float2 bv = *(const float2*)(bconv + col);
                if (ln) {
                    float2 wv = *(const float2*)(pw + col);
                    float2 bb = *(const float2*)(pb + col);
                    xv.x = wv.x * ((xv.x - mu) * rs) + bb.x;
                    xv.y = wv.y * ((xv.y - mu) * rs) + bb.y;
                }
                float2 o;
                o.x = fmaxf(acc[mi][nj][half * 2 + 0] + bv.x + xv.x, 0.f);
                o.y = fmaxf(acc[mi][nj][half * 2 + 1] + bv.y + xv.y, 0.f);
                *(float2*)(Xnext + (size_t)n * D + col) = o;
                ps += o.x + o.y;
                pq += o.x * o.x + o.y * o.y;
            }
        }
    }
    if (statsOut != nullptr) {
        #pragma unroll
        for (int o = 16; o > 0; o >>= 1) {
            ps += __shfl_down_sync(0xffffffffu, ps, o);
            pq += __shfl_down_sync(0xffffffffu, pq, o);
        }
        if (lane == 0) {
            atomicAdd(&statsOut[0], (double)ps);
            atomicAdd(&statsOut[1], (double)pq);
        }
    }
}

// ---------------- global mean pool + head ----------------
__global__ void pool_cnt(const int* __restrict__ batch, int Nn) {
    int i = blockIdx.x * blockDim.x + threadIdx.x;
    if (i < Nn) atomicAdd(&g_gcnt[batch[i]], 1);
}
__global__ void pool_sum(const float* __restrict__ X, const int* __restrict__ batch, int Nn) {
    int idx = blockIdx.x * blockDim.x + threadIdx.x;
    if (idx >= Nn * (D / 4)) return;
    int n = idx >> 6, c = idx & 63;
    float4 v = ((const float4*)X)[(size_t)n * (D / 4) + c];
    red_add_v4(g_pool + batch[n] * D + c * 4, v);
}
__global__ void head_kernel(const float* __restrict__ W1, const float* __restrict__ b1,
                            const float* __restrict__ W2, const float* __restrict__ b2,
                            const float* __restrict__ W3, const float* __restrict__ b3,
                            float* __restrict__ out) {
    __shared__ float g[D], h1[D], h2[D];
    int bg = blockIdx.x, j = threadIdx.x;
    float c = fmaxf((float)g_gcnt[bg], 1.f);
    g[j] = g_pool[bg * D + j] / c;
    __syncthreads();
    float acc = b1[j];
    for (int k = 0; k < D; k++) acc = fmaf(g[k], W1[k * D + j], acc);
    h1[j] = fmaxf(acc, 0.f);
    __syncthreads();
    acc = b2[j];
    for (int k = 0; k < D; k++) acc = fmaf(h1[k], W2[k * D + j], acc);
    h2[j] = fmaxf(acc, 0.f);
    __syncthreads();
    if (j < 4) {
        acc = b3[j];
        for (int k = 0; k < D; k++) acc = fmaf(h2[k], W3[k * 4 + j], acc);
        out[bg * 4 + j] = acc;
    }
}

// ---------------- launch ----------------
extern "C" void kernel_launch(void* const* d_in, const int* in_sizes, int n_in,
                              void* d_out, int out_size) {
    const float* x      = (const float*)d_in[0];
    const int*   ei     = (const int*)d_in[1];
    const int*   et     = (const int*)d_in[2];
    const int*   batch  = (const int*)d_in[3];
    const float* W_rel  = (const float*)d_in[4];
    const float* W_root = (const float*)d_in[5];
    const float* b_conv = (const float*)d_in[6];
    const float* ln_w   = (const float*)d_in[7];
    const float* ln_b   = (const float*)d_in[8];
    const float* W1 = (const float*)d_in[9];
    const float* b1 = (const float*)d_in[10];
    const float* W2 = (const float*)d_in[11];
    const float* b2 = (const float*)d_in[12];
    const float* W3 = (const float*)d_in[13];
    const float* b3 = (const float*)d_in[14];

    int E  = in_sizes[1] / 2;
    int Nn = in_sizes[0] / D;
    int M  = Nn * D;
    const int* src = ei;
    const int* dst = ei + E;
    int L = Nn * R;
    int nb = (L + 255) / 256;

    cudaFuncSetAttribute(rgcn_fused, cudaFuncAttributeMaxDynamicSharedMemorySize, SMEM_TOTAL);

    void *pCnt, *pStats, *pPool, *pGcnt, *pBh;
    cudaGetSymbolAddress(&pCnt, g_cnt);
    cudaGetSymbolAddress(&pStats, g_lnstats);
    cudaGetSymbolAddress(&pPool, g_pool);
    cudaGetSymbolAddress(&pGcnt, g_gcnt);
    cudaGetSymbolAddress(&pBh, g_Bh);
    double* pst = (double*)pStats;
    const __half* Bh0 = (const __half*)pBh;

    cudaMemsetAsync(pCnt, 0, (size_t)NMAX * R * sizeof(int));
    prep_B<<<dim3(NST, D / 32, 3), dim3(32, 8)>>>(W_rel, W_root);
    count_kernel<<<(E + 255) / 256, 256>>>(dst, et, E);
    scan_atomic<<<nb, 256>>>(L);
    place_kernel<<<(E + 255) / 256, 256>>>(src, dst, et, E);

    const float* cur = x;
    float* bufs[2];
    cudaGetSymbolAddress((void**)&bufs[0], g_X0);
    cudaGetSymbolAddress((void**)&bufs[1], g_X1);

    for (int l = 0; l < 3; l++) {
        const double* sp = (l > 0) ? (pst + (l - 1) * 2) : nullptr;
        const float* pw = (l > 0) ? (ln_w + (l - 1) * D) : nullptr;
        const float* pb = (l > 0) ? (ln_b + (l - 1) * D) : nullptr;
        float* nxt = bufs[l & 1];
        double* so = (l < 2) ? (pst + l * 2) : nullptr;
        rgcn_fused<<<NBLK, 384, SMEM_TOTAL>>>(
            cur, Bh0 + (size_t)l * NST * BTILEH, b_conv + l * D, nxt, Nn,
            pw, pb, sp, so, M);
        cur = nxt;
    }

    cudaMemsetAsync(pPool, 0, NG * D * sizeof(float));
    cudaMemsetAsync(pGcnt, 0, NG * sizeof(int));
    pool_cnt<<<(Nn + 255) / 256, 256>>>(batch, Nn);
    pool_sum<<<(Nn * (D / 4) + 255) / 256, 256>>>(cur, batch, Nn);
    head_kernel<<<NG, D>>>(W1, b1, W2, b2, W3, b3, (float*)d_out);
}